// round 6
// baseline (speedup 1.0000x reference)
#include <cuda_runtime.h>
#include <math.h>

#define Bc 2
#define Nn 2048
#define Dd 768
#define Hh 12
#define HDIM 64
#define SCALE 0.125f

// scratch (no cudaMalloc allowed)
__device__ float g_q [Bc*Hh*Nn*HDIM];   // [bh][n][d]
__device__ float g_kt[Bc*Hh*Nn*HDIM];   // [bh][d][n]  (transposed for coalesced key loads)
__device__ float g_v [Bc*Hh*Nn*HDIM];   // [bh][n][d]
__device__ float g_o [Bc*Nn*Dd];        // [b][n][h*64+d]
__device__ int   g_mask_width;          // 1 (byte bool) or 4 (int32/float32 word)

// ---------------------------------------------------------------------------
// Kernel 0: detect the storage width of the bool mask.
// Safe: reads exactly B*N = 4096 bytes, the minimum possible buffer size.
// uint8 bool  -> ~10% nonzero bytes at arbitrary offsets (incl. i%4==1)
// int32 0/1   -> nonzero only at i%4==0
// float32 1.0 -> nonzero only at i%4==2,3 (0x3F80 high bytes)
// => any nonzero byte at i%4==1 implies width 1; else width 4.
// Deterministic for fixed inputs.
// ---------------------------------------------------------------------------
__global__ void detect_mask_kernel(const unsigned char* __restrict__ m)
{
    __shared__ int s_w1;
    if (threadIdx.x == 0) s_w1 = 0;
    __syncthreads();
    int local = 0;
    for (int i = threadIdx.x; i < Bc * Nn; i += blockDim.x)
        if ((i & 3) == 1 && m[i] != 0) local = 1;
    if (local) atomicOr(&s_w1, 1);
    __syncthreads();
    if (threadIdx.x == 0) g_mask_width = s_w1 ? 1 : 4;
}

// ---------------------------------------------------------------------------
// Kernel 1: QKV projection  [4096,768] @ [768,2304] + bias, scatter epilogue
// ---------------------------------------------------------------------------
__global__ __launch_bounds__(256) void qkv_gemm_kernel(
    const float* __restrict__ x, const float* __restrict__ w,
    const float* __restrict__ bias)
{
    __shared__ __align__(16) float As[64][17];
    __shared__ __align__(16) float Bs[16][68];
    const int tid = threadIdx.x;
    const int tx = tid & 15, ty = tid >> 4;
    const int tx4 = tx * 4, ty4 = ty * 4;
    const int row0 = blockIdx.y * 64;
    const int col0 = blockIdx.x * 64;

    float acc[4][4] = {};
    for (int k0 = 0; k0 < Dd; k0 += 16) {
        #pragma unroll
        for (int u = 0; u < 4; u++) {
            int idx = tid * 4 + u;
            int r = idx >> 4, kk = idx & 15;
            As[r][kk] = x[(size_t)(row0 + r) * Dd + k0 + kk];
        }
        {
            int r = tid >> 4, c = (tid & 15) * 4;
            *(float4*)&Bs[r][c] =
                *(const float4*)&w[(size_t)(k0 + r) * (3 * Dd) + col0 + c];
        }
        __syncthreads();
        #pragma unroll
        for (int kk = 0; kk < 16; kk++) {
            float4 bb = *(const float4*)&Bs[kk][tx4];
            #pragma unroll
            for (int i = 0; i < 4; i++) {
                float a = As[ty4 + i][kk];
                acc[i][0] += a * bb.x; acc[i][1] += a * bb.y;
                acc[i][2] += a * bb.z; acc[i][3] += a * bb.w;
            }
        }
        __syncthreads();
    }

    // epilogue: whole 64-col tile lies inside one (part, head)
    const int part = col0 / Dd;           // 0=q 1=k 2=v
    const int h    = (col0 % Dd) >> 6;
    #pragma unroll
    for (int i = 0; i < 4; i++) {
        int r = row0 + ty4 + i;
        int b = r >> 11, n = r & 2047;
        int bh = b * Hh + h;
        #pragma unroll
        for (int j = 0; j < 4; j++) {
            int d = tx4 + j;
            float v = acc[i][j] + bias[col0 + d];
            if (part == 0)      g_q [((size_t)bh * Nn + n) * HDIM + d] = v;
            else if (part == 1) g_kt[((size_t)bh * HDIM + d) * Nn + n] = v;
            else                g_v [((size_t)bh * Nn + n) * HDIM + d] = v;
        }
    }
}

// ---------------------------------------------------------------------------
// Kernel 2: flash attention, 64q x 64k tiles, bias gather + mask fused
// ---------------------------------------------------------------------------
#define QS_OFF   0
#define KS_OFF   4352
#define VS_OFF   8704
#define SS_OFF   13056
#define PM_OFF   17408
#define PS_OFF   18432
#define M_OFF    19456
#define L_OFF    19520
#define AL_OFF   19584
#define BT_OFF   19648
#define MSK_OFF  19680
#define ATTN_SMEM_FLOATS 19744
#define ATTN_SMEM_BYTES  (ATTN_SMEM_FLOATS * 4)

__global__ __launch_bounds__(256) void attn_kernel(
    const int* __restrict__ dist, const unsigned char* __restrict__ mask,
    const float* __restrict__ bias_table)
{
    extern __shared__ __align__(16) float sm[];
    float* smQ  = sm + QS_OFF;
    float* smK  = sm + KS_OFF;
    float* smV  = sm + VS_OFF;
    float* smS  = sm + SS_OFF;
    float* smPM = sm + PM_OFF;
    float* smPS = sm + PS_OFF;
    float* smM  = sm + M_OFF;
    float* smL  = sm + L_OFF;
    float* smAl = sm + AL_OFF;
    float* smBT = sm + BT_OFF;
    float* smMsk= sm + MSK_OFF;

    const int tid = threadIdx.x;
    const int tx = tid & 15, ty = tid >> 4;
    const int tx4 = tx * 4, ty4 = ty * 4;
    const int bh = blockIdx.y;
    const int b = bh / Hh, h = bh % Hh;
    const int q0 = blockIdx.x * 64;
    const int mask_w = g_mask_width;

    const float* qptr = g_q  + (size_t)bh * Nn * HDIM + (size_t)q0 * HDIM;
    const float* ktp  = g_kt + (size_t)bh * HDIM * Nn;
    const float* vptr = g_v  + (size_t)bh * Nn * HDIM;

    // load Q tile [64][64] -> smQ (stride 68)
    #pragma unroll
    for (int u = 0; u < 4; u++) {
        int idx = tid + 256 * u;
        int r = idx >> 4, c4 = (idx & 15) * 4;
        *(float4*)&smQ[r * 68 + c4] = *(const float4*)&qptr[(size_t)r * HDIM + c4];
    }
    if (tid < 32) smBT[tid] = bias_table[tid * Hh + h];
    if (tid < 64) { smM[tid] = -INFINITY; smL[tid] = 0.f; }

    float o[4][4] = {};

    for (int k0 = 0; k0 < Nn; k0 += 64) {
        __syncthreads();   // prev PV done (and Q/stat init visible on first iter)
        // load K^T tile [d][m] and V tile [m][d]
        #pragma unroll
        for (int u = 0; u < 4; u++) {
            int idx = tid + 256 * u;
            int r = idx >> 4, c4 = (idx & 15) * 4;
            *(float4*)&smK[r * 68 + c4] = *(const float4*)&ktp [(size_t)r * Nn + k0 + c4];
            *(float4*)&smV[r * 68 + c4] = *(const float4*)&vptr[(size_t)(k0 + r) * HDIM + c4];
        }
        if (tid < 64) {
            int i = b * Nn + k0 + tid;
            bool masked;
            if (mask_w == 1) masked = (mask[i] != 0);
            else             masked = (((const unsigned int*)mask)[i] != 0u);
            smMsk[tid] = masked ? -INFINITY : 0.f;
        }
        __syncthreads();

        // S = Q @ K^T
        float s[4][4] = {};
        #pragma unroll 16
        for (int d = 0; d < 64; d++) {
            float4 bb = *(const float4*)&smK[d * 68 + tx4];
            #pragma unroll
            for (int i = 0; i < 4; i++) {
                float a = smQ[(ty4 + i) * 68 + d];
                s[i][0] += a * bb.x; s[i][1] += a * bb.y;
                s[i][2] += a * bb.z; s[i][3] += a * bb.w;
            }
        }
        // scale + relative-position bias + key mask
        #pragma unroll
        for (int i = 0; i < 4; i++) {
            const int* dp = dist + ((size_t)(b * Nn + q0 + ty4 + i)) * Nn + k0 + tx4;
            int4 dv = *(const int4*)dp;
            int d0 = min(max(dv.x, 0), 31), d1 = min(max(dv.y, 0), 31);
            int d2 = min(max(dv.z, 0), 31), d3 = min(max(dv.w, 0), 31);
            s[i][0] = s[i][0] * SCALE + smBT[d0] + smMsk[tx4 + 0];
            s[i][1] = s[i][1] * SCALE + smBT[d1] + smMsk[tx4 + 1];
            s[i][2] = s[i][2] * SCALE + smBT[d2] + smMsk[tx4 + 2];
            s[i][3] = s[i][3] * SCALE + smBT[d3] + smMsk[tx4 + 3];
        }
        // row-max partials
        #pragma unroll
        for (int i = 0; i < 4; i++)
            smPM[(ty4 + i) * 16 + tx] =
                fmaxf(fmaxf(s[i][0], s[i][1]), fmaxf(s[i][2], s[i][3]));
        __syncthreads();
        if (tid < 64) {
            float mo = smM[tid];
            float mx = mo;
            #pragma unroll
            for (int t = 0; t < 16; t++) mx = fmaxf(mx, smPM[tid * 16 + t]);
            smM[tid] = mx;
            // guard: if everything so far is -inf, alpha must be 0 (not nan)
            smAl[tid] = (mx == -INFINITY) ? 0.f : __expf(mo - mx);
        }
        __syncthreads();
        // p = exp(s - m), store to smS, partial sums, rescale O
        #pragma unroll
        for (int i = 0; i < 4; i++) {
            int row = ty4 + i;
            float mrow = smM[row];
            // guard: fully-masked-so-far row -> use 0 so exp(-inf - 0) = 0, not nan
            float mred = (mrow == -INFINITY) ? 0.f : mrow;
            float al = smAl[row];
            float sum = 0.f;
            #pragma unroll
            for (int j = 0; j < 4; j++) {
                float p = __expf(s[i][j] - mred);
                smS[row * 68 + tx4 + j] = p;
                sum += p;
                o[i][j] *= al;
            }
            smPS[row * 16 + tx] = sum;
        }
        __syncthreads();
        if (tid < 64) {
            float sum = 0.f;
            #pragma unroll
            for (int t = 0; t < 16; t++) sum += smPS[tid * 16 + t];
            smL[tid] = smL[tid] * smAl[tid] + sum;
        }
        // O += P @ V
        #pragma unroll 16
        for (int j = 0; j < 64; j++) {
            float4 vv = *(const float4*)&smV[j * 68 + tx4];
            #pragma unroll
            for (int i = 0; i < 4; i++) {
                float p = smS[(ty4 + i) * 68 + j];
                o[i][0] += p * vv.x; o[i][1] += p * vv.y;
                o[i][2] += p * vv.z; o[i][3] += p * vv.w;
            }
        }
    }
    __syncthreads();
    #pragma unroll
    for (int i = 0; i < 4; i++) {
        int row = ty4 + i;
        float l = smL[row];
        float inv = (l > 0.f) ? 1.f / l : 0.f;
        float4 r4 = make_float4(o[i][0] * inv, o[i][1] * inv,
                                o[i][2] * inv, o[i][3] * inv);
        *(float4*)&g_o[((size_t)(b * Nn + q0 + row)) * Dd + h * HDIM + tx4] = r4;
    }
}

// ---------------------------------------------------------------------------
// Kernel 3: output projection  [4096,768] @ [768,768] + bias -> d_out
// ---------------------------------------------------------------------------
__global__ __launch_bounds__(256) void out_gemm_kernel(
    const float* __restrict__ w, const float* __restrict__ bias,
    float* __restrict__ out)
{
    __shared__ __align__(16) float As[64][17];
    __shared__ __align__(16) float Bs[16][68];
    const int tid = threadIdx.x;
    const int tx = tid & 15, ty = tid >> 4;
    const int tx4 = tx * 4, ty4 = ty * 4;
    const int row0 = blockIdx.y * 64;
    const int col0 = blockIdx.x * 64;

    float acc[4][4] = {};
    for (int k0 = 0; k0 < Dd; k0 += 16) {
        #pragma unroll
        for (int u = 0; u < 4; u++) {
            int idx = tid * 4 + u;
            int r = idx >> 4, kk = idx & 15;
            As[r][kk] = g_o[(size_t)(row0 + r) * Dd + k0 + kk];
        }
        {
            int r = tid >> 4, c = (tid & 15) * 4;
            *(float4*)&Bs[r][c] = *(const float4*)&w[(size_t)(k0 + r) * Dd + col0 + c];
        }
        __syncthreads();
        #pragma unroll
        for (int kk = 0; kk < 16; kk++) {
            float4 bb = *(const float4*)&Bs[kk][tx4];
            #pragma unroll
            for (int i = 0; i < 4; i++) {
                float a = As[ty4 + i][kk];
                acc[i][0] += a * bb.x; acc[i][1] += a * bb.y;
                acc[i][2] += a * bb.z; acc[i][3] += a * bb.w;
            }
        }
        __syncthreads();
    }
    #pragma unroll
    for (int i = 0; i < 4; i++) {
        int r = row0 + ty4 + i;
        int c = col0 + tx4;
        float4 r4 = make_float4(acc[i][0] + bias[c + 0], acc[i][1] + bias[c + 1],
                                acc[i][2] + bias[c + 2], acc[i][3] + bias[c + 3]);
        *(float4*)&out[(size_t)r * Dd + c] = r4;
    }
}

// ---------------------------------------------------------------------------
extern "C" void kernel_launch(void* const* d_in, const int* in_sizes, int n_in,
                              void* d_out, int out_size)
{
    const float*         x          = (const float*)d_in[0];
    const int*           dist       = (const int*)d_in[1];
    const unsigned char* mask       = (const unsigned char*)d_in[2];
    const float*         qkv_w      = (const float*)d_in[3];
    const float*         qkv_b      = (const float*)d_in[4];
    const float*         out_w      = (const float*)d_in[5];
    const float*         out_b      = (const float*)d_in[6];
    const float*         bias_table = (const float*)d_in[7];
    float*               out        = (float*)d_out;

    cudaFuncSetAttribute(attn_kernel,
                         cudaFuncAttributeMaxDynamicSharedMemorySize,
                         ATTN_SMEM_BYTES);

    detect_mask_kernel<<<1, 256>>>(mask);
    qkv_gemm_kernel<<<dim3(36, 64), 256>>>(x, qkv_w, qkv_b);
    attn_kernel<<<dim3(Nn / 64, Bc * Hh), 256, ATTN_SMEM_BYTES>>>(dist, mask, bias_table);
    out_gemm_kernel<<<dim3(12, 64), 256>>>(out_w, out_b, out);
}

// round 8
// speedup vs baseline: 1.0738x; 1.0738x over previous
#include <cuda_runtime.h>
#include <math.h>

#define Bc 2
#define Nn 2048
#define Dd 768
#define Hh 12
#define HDIM 64
#define SCALE 0.125f

// scratch (no cudaMalloc allowed)
__device__ float g_q [Bc*Hh*Nn*HDIM];   // [bh][n][d]
__device__ float g_kt[Bc*Hh*Nn*HDIM];   // [bh][d][n]
__device__ float g_v [Bc*Hh*Nn*HDIM];   // [bh][n][d]
__device__ float g_o [Bc*Nn*Dd];        // [b][n][h*64+d]
__device__ int   g_mask_width;          // 1 (byte bool) or 4 (word)

// ---------------------------------------------------------------------------
// Kernel 0: detect mask storage width (byte-bool vs 4-byte word).
// ---------------------------------------------------------------------------
__global__ void detect_mask_kernel(const unsigned char* __restrict__ m)
{
    __shared__ int s_w1;
    if (threadIdx.x == 0) s_w1 = 0;
    __syncthreads();
    int local = 0;
    for (int i = threadIdx.x; i < Bc * Nn; i += blockDim.x)
        if ((i & 3) == 1 && m[i] != 0) local = 1;
    if (local) atomicOr(&s_w1, 1);
    __syncthreads();
    if (threadIdx.x == 0) g_mask_width = s_w1 ? 1 : 4;
}

// ---------------------------------------------------------------------------
// Kernel 1: QKV projection  [4096,768]@[768,2304]+bias, 128x128 tile,
// 8x8 micro-tile, double-buffered BK=8, scatter epilogue to q/kt/v.
// ---------------------------------------------------------------------------
__global__ __launch_bounds__(256) void qkv_gemm_kernel(
    const float* __restrict__ x, const float* __restrict__ w,
    const float* __restrict__ bias)
{
    const int NT = 3 * Dd;   // 2304
    __shared__ __align__(16) float As[2][8][128];
    __shared__ __align__(16) float Bs[2][8][128];
    const int tid = threadIdx.x;
    const int tx = tid & 15, ty = tid >> 4;
    const int tx4 = tx * 4, ty4 = ty * 4;
    const int row0 = blockIdx.y * 128;
    const int col0 = blockIdx.x * 128;

    const int lar = tid >> 1, lak = (tid & 1) * 4;   // As: row, k-offset
    const int lbr = tid >> 5, lbc = (tid & 31) * 4;  // Bs: k-row, col
    const float* xA = x + (size_t)(row0 + lar) * Dd + lak;
    const float* wB = w + (size_t)lbr * NT + col0 + lbc;

    float4 pa = *(const float4*)xA;
    float4 pb = *(const float4*)wB;
    As[0][lak+0][lar] = pa.x; As[0][lak+1][lar] = pa.y;
    As[0][lak+2][lar] = pa.z; As[0][lak+3][lar] = pa.w;
    *(float4*)&Bs[0][lbr][lbc] = pb;
    __syncthreads();

    float acc[8][8] = {};
    int buf = 0;
    for (int kt = 0; kt < 96; kt++) {
        if (kt < 95) {
            pa = *(const float4*)(xA + (kt + 1) * 8);
            pb = *(const float4*)(wB + (size_t)(kt + 1) * 8 * NT);
        }
        #pragma unroll
        for (int k = 0; k < 8; k++) {
            float a[8], b[8];
            *(float4*)&a[0] = *(const float4*)&As[buf][k][ty4];
            *(float4*)&a[4] = *(const float4*)&As[buf][k][64 + ty4];
            *(float4*)&b[0] = *(const float4*)&Bs[buf][k][tx4];
            *(float4*)&b[4] = *(const float4*)&Bs[buf][k][64 + tx4];
            #pragma unroll
            for (int i = 0; i < 8; i++)
                #pragma unroll
                for (int j = 0; j < 8; j++)
                    acc[i][j] += a[i] * b[j];
        }
        if (kt < 95) {
            As[buf^1][lak+0][lar] = pa.x; As[buf^1][lak+1][lar] = pa.y;
            As[buf^1][lak+2][lar] = pa.z; As[buf^1][lak+3][lar] = pa.w;
            *(float4*)&Bs[buf^1][lbr][lbc] = pb;
        }
        __syncthreads();
        buf ^= 1;
    }

    const int part = col0 / Dd;           // 0=q 1=k 2=v (128 | 768 boundaries)
    #pragma unroll
    for (int i = 0; i < 8; i++) {
        int r = row0 + (i >> 2) * 64 + ty4 + (i & 3);
        int b = r >> 11, n = r & 2047;
        #pragma unroll
        for (int j = 0; j < 8; j++) {
            int c = col0 + (j >> 2) * 64 + tx4 + (j & 3);
            int h = (c - part * Dd) >> 6;
            int d = c & 63;
            int bh = b * Hh + h;
            float v = acc[i][j] + bias[c];
            if (part == 0)      g_q [((size_t)bh * Nn + n) * HDIM + d] = v;
            else if (part == 1) g_kt[((size_t)bh * HDIM + d) * Nn + n] = v;
            else                g_v [((size_t)bh * Nn + n) * HDIM + d] = v;
        }
    }
}

// ---------------------------------------------------------------------------
// Kernel 2: flash attention, 64q x 64k tiles, shfl softmax, float4 quads
// ---------------------------------------------------------------------------
#define QS_OFF   0
#define KS_OFF   4352
#define VS_OFF   8704
#define SS_OFF   13056
#define BT_OFF   17408
#define MSK_OFF  17440
#define ATTN_SMEM_FLOATS 17504
#define ATTN_SMEM_BYTES  (ATTN_SMEM_FLOATS * 4)

__global__ __launch_bounds__(256) void attn_kernel(
    const int* __restrict__ dist, const unsigned char* __restrict__ mask,
    const float* __restrict__ bias_table)
{
    extern __shared__ __align__(16) float sm[];
    float* smQ  = sm + QS_OFF;
    float* smK  = sm + KS_OFF;   // [d][m]
    float* smV  = sm + VS_OFF;   // [m][d]
    float* smS  = sm + SS_OFF;   // [q][m]
    float* smBT = sm + BT_OFF;
    float* smMsk= sm + MSK_OFF;

    const int tid = threadIdx.x;
    const int tx = tid & 15, ty = tid >> 4;
    const int tx4 = tx * 4, ty4 = ty * 4;
    const int bh = blockIdx.y;
    const int b = bh / Hh, h = bh % Hh;
    const int q0 = blockIdx.x * 64;
    const int mask_w = g_mask_width;

    const float* qptr = g_q  + (size_t)bh * Nn * HDIM + (size_t)q0 * HDIM;
    const float* ktp  = g_kt + (size_t)bh * HDIM * Nn;
    const float* vptr = g_v  + (size_t)bh * Nn * HDIM;

    // load Q tile [64][64] (stride 68)
    #pragma unroll
    for (int u = 0; u < 4; u++) {
        int idx = tid + 256 * u;
        int r = idx >> 4, c4 = (idx & 15) * 4;
        *(float4*)&smQ[r * 68 + c4] = *(const float4*)&qptr[(size_t)r * HDIM + c4];
    }
    if (tid < 32) smBT[tid] = bias_table[tid * Hh + h];

    float o[4][4] = {};
    float m[4] = {-INFINITY, -INFINITY, -INFINITY, -INFINITY};
    float l[4] = {};

    for (int k0 = 0; k0 < Nn; k0 += 64) {
        __syncthreads();   // prev PV done with smK/V/S (Q/BT visible 1st iter)
        #pragma unroll
        for (int u = 0; u < 4; u++) {
            int idx = tid + 256 * u;
            int r = idx >> 4, c4 = (idx & 15) * 4;
            *(float4*)&smK[r * 68 + c4] = *(const float4*)&ktp [(size_t)r * Nn + k0 + c4];
            *(float4*)&smV[r * 68 + c4] = *(const float4*)&vptr[(size_t)(k0 + r) * HDIM + c4];
        }
        if (tid < 64) {
            int i = b * Nn + k0 + tid;
            bool masked = (mask_w == 1) ? (mask[i] != 0)
                                        : (((const unsigned int*)mask)[i] != 0u);
            smMsk[tid] = masked ? -INFINITY : 0.f;
        }
        __syncthreads();

        // S = Q @ K^T  (64 FFMA per 8 LDS128)
        float s[4][4] = {};
        #pragma unroll 8
        for (int d0 = 0; d0 < 64; d0 += 4) {
            float4 k0v = *(const float4*)&smK[(d0+0) * 68 + tx4];
            float4 k1v = *(const float4*)&smK[(d0+1) * 68 + tx4];
            float4 k2v = *(const float4*)&smK[(d0+2) * 68 + tx4];
            float4 k3v = *(const float4*)&smK[(d0+3) * 68 + tx4];
            #pragma unroll
            for (int i = 0; i < 4; i++) {
                float4 qq = *(const float4*)&smQ[(ty4 + i) * 68 + d0];
                s[i][0] += qq.x*k0v.x + qq.y*k1v.x + qq.z*k2v.x + qq.w*k3v.x;
                s[i][1] += qq.x*k0v.y + qq.y*k1v.y + qq.z*k2v.y + qq.w*k3v.y;
                s[i][2] += qq.x*k0v.z + qq.y*k1v.z + qq.z*k2v.z + qq.w*k3v.z;
                s[i][3] += qq.x*k0v.w + qq.y*k1v.w + qq.z*k2v.w + qq.w*k3v.w;
            }
        }
        // scale + relative-position bias + key mask
        #pragma unroll
        for (int i = 0; i < 4; i++) {
            const int* dp = dist + ((size_t)(b * Nn + q0 + ty4 + i)) * Nn + k0 + tx4;
            int4 dv = *(const int4*)dp;
            int d0 = min(max(dv.x, 0), 31), d1 = min(max(dv.y, 0), 31);
            int d2 = min(max(dv.z, 0), 31), d3 = min(max(dv.w, 0), 31);
            s[i][0] = s[i][0] * SCALE + smBT[d0] + smMsk[tx4 + 0];
            s[i][1] = s[i][1] * SCALE + smBT[d1] + smMsk[tx4 + 1];
            s[i][2] = s[i][2] * SCALE + smBT[d2] + smMsk[tx4 + 2];
            s[i][3] = s[i][3] * SCALE + smBT[d3] + smMsk[tx4 + 3];
        }
        // online softmax, all in registers + shfl across the 16-lane tx group
        #pragma unroll
        for (int i = 0; i < 4; i++) {
            float tm = fmaxf(fmaxf(s[i][0], s[i][1]), fmaxf(s[i][2], s[i][3]));
            #pragma unroll
            for (int off = 8; off; off >>= 1)
                tm = fmaxf(tm, __shfl_xor_sync(0xffffffffu, tm, off));
            float mo = m[i];
            float mn = fmaxf(mo, tm);
            float al   = (mn == -INFINITY) ? 0.f : __expf(mo - mn);
            float mred = (mn == -INFINITY) ? 0.f : mn;
            float sum = 0.f;
            int row = ty4 + i;
            #pragma unroll
            for (int j = 0; j < 4; j++) {
                float p = __expf(s[i][j] - mred);
                smS[row * 68 + tx4 + j] = p;
                sum += p;
                o[i][j] *= al;
            }
            #pragma unroll
            for (int off = 8; off; off >>= 1)
                sum += __shfl_xor_sync(0xffffffffu, sum, off);
            l[i] = l[i] * al + sum;
            m[i] = mn;
        }
        __syncthreads();

        // O += P @ V  (64 FFMA per 8 LDS128)
        #pragma unroll 8
        for (int j0 = 0; j0 < 64; j0 += 4) {
            float4 v0 = *(const float4*)&smV[(j0+0) * 68 + tx4];
            float4 v1 = *(const float4*)&smV[(j0+1) * 68 + tx4];
            float4 v2 = *(const float4*)&smV[(j0+2) * 68 + tx4];
            float4 v3 = *(const float4*)&smV[(j0+3) * 68 + tx4];
            #pragma unroll
            for (int i = 0; i < 4; i++) {
                float4 pp = *(const float4*)&smS[(ty4 + i) * 68 + j0];
                o[i][0] += pp.x*v0.x + pp.y*v1.x + pp.z*v2.x + pp.w*v3.x;
                o[i][1] += pp.x*v0.y + pp.y*v1.y + pp.z*v2.y + pp.w*v3.y;
                o[i][2] += pp.x*v0.z + pp.y*v1.z + pp.z*v2.z + pp.w*v3.z;
                o[i][3] += pp.x*v0.w + pp.y*v1.w + pp.z*v2.w + pp.w*v3.w;
            }
        }
    }
    #pragma unroll
    for (int i = 0; i < 4; i++) {
        int row = ty4 + i;
        float inv = (l[i] > 0.f) ? 1.f / l[i] : 0.f;
        float4 r4 = make_float4(o[i][0] * inv, o[i][1] * inv,
                                o[i][2] * inv, o[i][3] * inv);
        *(float4*)&g_o[((size_t)(b * Nn + q0 + row)) * Dd + h * HDIM + tx4] = r4;
    }
}

// ---------------------------------------------------------------------------
// Kernel 3: output projection  [4096,768]@[768,768]+bias, same GEMM scheme
// ---------------------------------------------------------------------------
__global__ __launch_bounds__(256) void out_gemm_kernel(
    const float* __restrict__ w, const float* __restrict__ bias,
    float* __restrict__ out)
{
    const int NT = Dd;   // 768
    __shared__ __align__(16) float As[2][8][128];
    __shared__ __align__(16) float Bs[2][8][128];
    const int tid = threadIdx.x;
    const int tx = tid & 15, ty = tid >> 4;
    const int tx4 = tx * 4, ty4 = ty * 4;
    const int row0 = blockIdx.y * 128;
    const int col0 = blockIdx.x * 128;

    const int lar = tid >> 1, lak = (tid & 1) * 4;
    const int lbr = tid >> 5, lbc = (tid & 31) * 4;
    const float* xA = g_o + (size_t)(row0 + lar) * Dd + lak;
    const float* wB = w + (size_t)lbr * NT + col0 + lbc;

    float4 pa = *(const float4*)xA;
    float4 pb = *(const float4*)wB;
    As[0][lak+0][lar] = pa.x; As[0][lak+1][lar] = pa.y;
    As[0][lak+2][lar] = pa.z; As[0][lak+3][lar] = pa.w;
    *(float4*)&Bs[0][lbr][lbc] = pb;
    __syncthreads();

    float acc[8][8] = {};
    int buf = 0;
    for (int kt = 0; kt < 96; kt++) {
        if (kt < 95) {
            pa = *(const float4*)(xA + (kt + 1) * 8);
            pb = *(const float4*)(wB + (size_t)(kt + 1) * 8 * NT);
        }
        #pragma unroll
        for (int k = 0; k < 8; k++) {
            float a[8], b[8];
            *(float4*)&a[0] = *(const float4*)&As[buf][k][ty4];
            *(float4*)&a[4] = *(const float4*)&As[buf][k][64 + ty4];
            *(float4*)&b[0] = *(const float4*)&Bs[buf][k][tx4];
            *(float4*)&b[4] = *(const float4*)&Bs[buf][k][64 + tx4];
            #pragma unroll
            for (int i = 0; i < 8; i++)
                #pragma unroll
                for (int j = 0; j < 8; j++)
                    acc[i][j] += a[i] * b[j];
        }
        if (kt < 95) {
            As[buf^1][lak+0][lar] = pa.x; As[buf^1][lak+1][lar] = pa.y;
            As[buf^1][lak+2][lar] = pa.z; As[buf^1][lak+3][lar] = pa.w;
            *(float4*)&Bs[buf^1][lbr][lbc] = pb;
        }
        __syncthreads();
        buf ^= 1;
    }

    #pragma unroll
    for (int i = 0; i < 8; i++) {
        int r = row0 + (i >> 2) * 64 + ty4 + (i & 3);
        #pragma unroll
        for (int jh = 0; jh < 2; jh++) {
            int c = col0 + jh * 64 + tx4;
            float4 r4 = make_float4(acc[i][jh*4+0] + bias[c+0],
                                    acc[i][jh*4+1] + bias[c+1],
                                    acc[i][jh*4+2] + bias[c+2],
                                    acc[i][jh*4+3] + bias[c+3]);
            *(float4*)&out[(size_t)r * Dd + c] = r4;
        }
    }
}

// ---------------------------------------------------------------------------
extern "C" void kernel_launch(void* const* d_in, const int* in_sizes, int n_in,
                              void* d_out, int out_size)
{
    const float*         x          = (const float*)d_in[0];
    const int*           dist       = (const int*)d_in[1];
    const unsigned char* mask       = (const unsigned char*)d_in[2];
    const float*         qkv_w      = (const float*)d_in[3];
    const float*         qkv_b      = (const float*)d_in[4];
    const float*         out_w      = (const float*)d_in[5];
    const float*         out_b      = (const float*)d_in[6];
    const float*         bias_table = (const float*)d_in[7];
    float*               out        = (float*)d_out;

    cudaFuncSetAttribute(attn_kernel,
                         cudaFuncAttributeMaxDynamicSharedMemorySize,
                         ATTN_SMEM_BYTES);

    detect_mask_kernel<<<1, 256>>>(mask);
    qkv_gemm_kernel<<<dim3(18, 32), 256>>>(x, qkv_w, qkv_b);
    attn_kernel<<<dim3(Nn / 64, Bc * Hh), 256, ATTN_SMEM_BYTES>>>(dist, mask, bias_table);
    out_gemm_kernel<<<dim3(6, 32), 256>>>(out_w, out_b, out);
}

// round 15
// speedup vs baseline: 1.3258x; 1.2347x over previous
#include <cuda_runtime.h>
#include <cuda_bf16.h>
#include <cstdint>
#include <math.h>

#define Bc 2
#define Nn 2048
#define Dd 768
#define Hh 12
#define HDIM 64
#define SCALE 0.125f

// ---------------------------------------------------------------------------
// scratch (no cudaMalloc allowed)
// ---------------------------------------------------------------------------
__device__ float g_q [Bc*Hh*Nn*HDIM];   // [bh][n][d]
__device__ float g_kt[Bc*Hh*Nn*HDIM];   // [bh][d][n]
__device__ float g_v [Bc*Hh*Nn*HDIM];   // [bh][n][d]
__device__ float g_o [Bc*Nn*Dd];        // [b][n][h*64+d]
__device__ int   g_mask_width;

// bf16 split operands
__device__ __nv_bfloat16 g_xhi[Bc*Nn*Dd],  g_xlo[Bc*Nn*Dd];      // x      [4096][768]
__device__ __nv_bfloat16 g_ohi[Bc*Nn*Dd],  g_olo[Bc*Nn*Dd];      // attn O [4096][768]
__device__ __nv_bfloat16 g_wqT_hi[3*Dd*Dd], g_wqT_lo[3*Dd*Dd];   // qkv_w^T [2304][768]
__device__ __nv_bfloat16 g_woT_hi[Dd*Dd],   g_woT_lo[Dd*Dd];     // out_w^T [768][768]

__device__ __forceinline__ uint32_t smem_to_u32(const void* p) {
    uint32_t a;
    asm("{ .reg .u64 t; cvta.to.shared.u64 t, %1; cvt.u32.u64 %0, t; }"
        : "=r"(a) : "l"(p));
    return a;
}

#define LDMATRIX_X4(r0, r1, r2, r3, addr)                                   \
    asm volatile("ldmatrix.sync.aligned.m8n8.x4.shared.b16 {%0,%1,%2,%3}, [%4];" \
        : "=r"(r0), "=r"(r1), "=r"(r2), "=r"(r3) : "r"(addr))

#define MMA_BF16(c, a, b0, b1)                                              \
    asm volatile("mma.sync.aligned.m16n8k16.row.col.f32.bf16.bf16.f32 "     \
        "{%0,%1,%2,%3}, {%4,%5,%6,%7}, {%8,%9}, {%0,%1,%2,%3};"             \
        : "+f"((c)[0]), "+f"((c)[1]), "+f"((c)[2]), "+f"((c)[3])            \
        : "r"((a)[0]), "r"((a)[1]), "r"((a)[2]), "r"((a)[3]),               \
          "r"(b0), "r"(b1))

// ---------------------------------------------------------------------------
// Kernel 0: detect mask storage width
// ---------------------------------------------------------------------------
__global__ void detect_mask_kernel(const unsigned char* __restrict__ m)
{
    __shared__ int s_w1;
    if (threadIdx.x == 0) s_w1 = 0;
    __syncthreads();
    int local = 0;
    for (int i = threadIdx.x; i < Bc * Nn; i += blockDim.x)
        if ((i & 3) == 1 && m[i] != 0) local = 1;
    if (local) atomicOr(&s_w1, 1);
    __syncthreads();
    if (threadIdx.x == 0) g_mask_width = s_w1 ? 1 : 4;
}

// ---------------------------------------------------------------------------
// prep: elementwise fp32 -> bf16 hi/lo split
// ---------------------------------------------------------------------------
__global__ __launch_bounds__(256) void split_fp32_kernel(
    const float* __restrict__ src, __nv_bfloat16* __restrict__ hi,
    __nv_bfloat16* __restrict__ lo, int n)
{
    int i = blockIdx.x * 256 + threadIdx.x;
    if (i < n) {
        float v = src[i];
        __nv_bfloat16 h = __float2bfloat16(v);
        hi[i] = h;
        lo[i] = __float2bfloat16(v - __bfloat162float(h));
    }
}

// ---------------------------------------------------------------------------
// prep: transpose + split  w[R][C] -> wT_hi/lo[C][R]
// ---------------------------------------------------------------------------
__global__ __launch_bounds__(256) void tsplit_kernel(
    const float* __restrict__ w, __nv_bfloat16* __restrict__ thi,
    __nv_bfloat16* __restrict__ tlo, int R, int C)
{
    __shared__ float t[32][33];
    int c0 = blockIdx.x * 32, r0 = blockIdx.y * 32;
    int tx = threadIdx.x & 31, ty = threadIdx.x >> 5;   // 32 x 8
    #pragma unroll
    for (int i = 0; i < 32; i += 8)
        t[ty + i][tx] = w[(size_t)(r0 + ty + i) * C + c0 + tx];
    __syncthreads();
    #pragma unroll
    for (int i = 0; i < 32; i += 8) {
        float v = t[tx][ty + i];
        __nv_bfloat16 h = __float2bfloat16(v);
        size_t o = (size_t)(c0 + ty + i) * R + r0 + tx;
        thi[o] = h;
        tlo[o] = __float2bfloat16(v - __bfloat162float(h));
    }
}

// ---------------------------------------------------------------------------
// mma.sync projection GEMM: C[4096,NT] = (Ah+Al)[4096,768] @ (Bh+Bl)^T
// block 128x128, 8 warps (4m x 2n), warp tile 32x64, BK=32, split 3-term.
// MODE 0: qkv scatter -> g_q/g_kt/g_v, MODE 1: -> outp with bias.
// ---------------------------------------------------------------------------
// smem layout (bytes): 4 tiles of 128 rows x 40 bf16 (80B rows)
#define AH_OFF 0
#define AL_OFF 10240
#define BH_OFF 20480
#define BL_OFF 30720
#define HMMA_SMEM_BYTES 66560   // epilogue reuses as float sT[128][129] (66048)

template<int MODE>
__global__ __launch_bounds__(256) void hmma_proj_kernel(
    const __nv_bfloat16* __restrict__ Ah, const __nv_bfloat16* __restrict__ Al,
    const __nv_bfloat16* __restrict__ Bh, const __nv_bfloat16* __restrict__ Bl,
    const float* __restrict__ bias, float* __restrict__ outp)
{
    extern __shared__ __align__(16) char smc[];
    const uint32_t sb = smem_to_u32(smc);

    const int tid  = threadIdx.x;
    const int warp = tid >> 5, lane = tid & 31;
    const int wm = warp & 3, wn = warp >> 2;
    const int row0 = blockIdx.y * 128;
    const int col0 = blockIdx.x * 128;

    const __nv_bfloat16* pA[2] = { Ah + (size_t)row0 * Dd, Al + (size_t)row0 * Dd };
    const __nv_bfloat16* pB[2] = { Bh + (size_t)col0 * Dd, Bl + (size_t)col0 * Dd };

    float acc[2][8][4] = {};

    // ldmatrix address components
    const int la = lane & 15;               // A: row within 16
    const int ha = (lane >> 4) << 3;        // A: k-half select
    const int lb = (lane & 7) + ((lane >> 4) << 3);   // B: row within 16
    const int kb = ((lane >> 3) & 1) << 3;  // B: k-half select

    const int ldrow = tid >> 2;             // gmem->smem: 128 rows x 4 segs
    const int ldseg = tid & 3;

    for (int kc = 0; kc < Dd / 32; kc++) {
        __syncthreads();
        {
            const int gcol = kc * 32 + ldseg * 8;
            const uint32_t so = (uint32_t)(ldrow * 80 + ldseg * 16);
            *(uint4*)(smc + AH_OFF + so)       = *(const uint4*)(pA[0] + (size_t)ldrow * Dd + gcol);
            *(uint4*)(smc + AL_OFF + so)       = *(const uint4*)(pA[1] + (size_t)ldrow * Dd + gcol);
            *(uint4*)(smc + BH_OFF + so)       = *(const uint4*)(pB[0] + (size_t)ldrow * Dd + gcol);
            *(uint4*)(smc + BL_OFF + so)       = *(const uint4*)(pB[1] + (size_t)ldrow * Dd + gcol);
            const int ldrow2 = ldrow + 64;    // second half of rows
            const uint32_t so2 = (uint32_t)(ldrow2 * 80 + ldseg * 16);
            *(uint4*)(smc + AH_OFF + so2)      = *(const uint4*)(pA[0] + (size_t)ldrow2 * Dd + gcol);
            *(uint4*)(smc + AL_OFF + so2)      = *(const uint4*)(pA[1] + (size_t)ldrow2 * Dd + gcol);
            *(uint4*)(smc + BH_OFF + so2)      = *(const uint4*)(pB[0] + (size_t)ldrow2 * Dd + gcol);
            *(uint4*)(smc + BL_OFF + so2)      = *(const uint4*)(pB[1] + (size_t)ldrow2 * Dd + gcol);
        }
        __syncthreads();

        #pragma unroll
        for (int ks = 0; ks < 32; ks += 16) {
            uint32_t ahi[2][4], alo[2][4];
            #pragma unroll
            for (int mf = 0; mf < 2; mf++) {
                uint32_t ar = (uint32_t)((wm * 32 + mf * 16 + la) * 80 + (ks + ha) * 2);
                LDMATRIX_X4(ahi[mf][0], ahi[mf][1], ahi[mf][2], ahi[mf][3],
                            sb + AH_OFF + ar);
                LDMATRIX_X4(alo[mf][0], alo[mf][1], alo[mf][2], alo[mf][3],
                            sb + AL_OFF + ar);
            }
            #pragma unroll
            for (int g = 0; g < 4; g++) {
                uint32_t br = (uint32_t)((wn * 64 + g * 16 + lb) * 80 + (ks + kb) * 2);
                uint32_t bh0, bh1, bh2, bh3, bl0, bl1, bl2, bl3;
                LDMATRIX_X4(bh0, bh1, bh2, bh3, sb + BH_OFF + br);
                LDMATRIX_X4(bl0, bl1, bl2, bl3, sb + BL_OFF + br);
                #pragma unroll
                for (int mf = 0; mf < 2; mf++) {
                    MMA_BF16(acc[mf][2*g],   ahi[mf], bh0, bh1);
                    MMA_BF16(acc[mf][2*g],   alo[mf], bh0, bh1);
                    MMA_BF16(acc[mf][2*g],   ahi[mf], bl0, bl1);
                    MMA_BF16(acc[mf][2*g+1], ahi[mf], bh2, bh3);
                    MMA_BF16(acc[mf][2*g+1], alo[mf], bh2, bh3);
                    MMA_BF16(acc[mf][2*g+1], ahi[mf], bl2, bl3);
                }
            }
        }
    }

    // stage f32 tile to smem (reuse operand buffers), then coalesced scatter
    __syncthreads();
    float* sT = (float*)smc;
    const int qr = lane >> 2, qc = (lane & 3) * 2;
    #pragma unroll
    for (int mf = 0; mf < 2; mf++)
        #pragma unroll
        for (int nf = 0; nf < 8; nf++) {
            int m = wm * 32 + mf * 16 + qr;
            int n = wn * 64 + nf * 8 + qc;
            sT[m * 129 + n]           = acc[mf][nf][0];
            sT[m * 129 + n + 1]       = acc[mf][nf][1];
            sT[(m + 8) * 129 + n]     = acc[mf][nf][2];
            sT[(m + 8) * 129 + n + 1] = acc[mf][nf][3];
        }
    __syncthreads();

    if (MODE == 1) {
        #pragma unroll 4
        for (int u = 0; u < 16; u++) {
            int fid = tid + 256 * u;
            int m = fid >> 5, c4 = (fid & 31) * 4;
            float4 v = make_float4(sT[m*129+c4]   + bias[col0+c4],
                                   sT[m*129+c4+1] + bias[col0+c4+1],
                                   sT[m*129+c4+2] + bias[col0+c4+2],
                                   sT[m*129+c4+3] + bias[col0+c4+3]);
            *(float4*)&outp[(size_t)(row0 + m) * Dd + col0 + c4] = v;
        }
    } else {
        const int part = col0 / Dd;          // 0=q 1=k 2=v
        const int h0 = (col0 % Dd) >> 6;
        const int b = row0 >> 11, n0 = row0 & 2047;
        if (part != 1) {
            float* dst = (part == 0) ? g_q : g_v;
            #pragma unroll 4
            for (int u = 0; u < 16; u++) {
                int fid = tid + 256 * u;
                int m = fid >> 5, c4 = (fid & 31) * 4;
                int h = h0 + (c4 >> 6), d = c4 & 63;
                float4 v = make_float4(sT[m*129+c4]   + bias[col0+c4],
                                       sT[m*129+c4+1] + bias[col0+c4+1],
                                       sT[m*129+c4+2] + bias[col0+c4+2],
                                       sT[m*129+c4+3] + bias[col0+c4+3]);
                *(float4*)&dst[(((size_t)(b * Hh + h)) * Nn + n0 + m) * HDIM + d] = v;
            }
        } else {
            #pragma unroll 4
            for (int u = 0; u < 16; u++) {
                int idx = tid + 256 * u;
                int c = idx >> 5;            // column 0..127
                int m4 = (idx & 31) * 4;
                int h = h0 + (c >> 6), d = c & 63;
                float bsc = bias[col0 + c];
                float4 v = make_float4(sT[(m4+0)*129+c] + bsc, sT[(m4+1)*129+c] + bsc,
                                       sT[(m4+2)*129+c] + bsc, sT[(m4+3)*129+c] + bsc);
                *(float4*)&g_kt[(((size_t)(b * Hh + h)) * HDIM + d) * Nn + n0 + m4] = v;
            }
        }
    }
}

// ---------------------------------------------------------------------------
// Kernel: flash attention (fp32, unchanged from passing R8 version)
// ---------------------------------------------------------------------------
#define QS_OFF   0
#define KS_OFF   4352
#define VS_OFF   8704
#define SS_OFF   13056
#define BT_OFF   17408
#define MSK_OFF  17440
#define ATTN_SMEM_FLOATS 17504
#define ATTN_SMEM_BYTES  (ATTN_SMEM_FLOATS * 4)

__global__ __launch_bounds__(256) void attn_kernel(
    const int* __restrict__ dist, const unsigned char* __restrict__ mask,
    const float* __restrict__ bias_table)
{
    extern __shared__ __align__(16) float sm[];
    float* smQ  = sm + QS_OFF;
    float* smK  = sm + KS_OFF;
    float* smV  = sm + VS_OFF;
    float* smS  = sm + SS_OFF;
    float* smBT = sm + BT_OFF;
    float* smMsk= sm + MSK_OFF;

    const int tid = threadIdx.x;
    const int tx = tid & 15, ty = tid >> 4;
    const int tx4 = tx * 4, ty4 = ty * 4;
    const int bh = blockIdx.y;
    const int b = bh / Hh, h = bh % Hh;
    const int q0 = blockIdx.x * 64;
    const int mask_w = g_mask_width;

    const float* qptr = g_q  + (size_t)bh * Nn * HDIM + (size_t)q0 * HDIM;
    const float* ktp  = g_kt + (size_t)bh * HDIM * Nn;
    const float* vptr = g_v  + (size_t)bh * Nn * HDIM;

    #pragma unroll
    for (int u = 0; u < 4; u++) {
        int idx = tid + 256 * u;
        int r = idx >> 4, c4 = (idx & 15) * 4;
        *(float4*)&smQ[r * 68 + c4] = *(const float4*)&qptr[(size_t)r * HDIM + c4];
    }
    if (tid < 32) smBT[tid] = bias_table[tid * Hh + h];

    float o[4][4] = {};
    float m[4] = {-INFINITY, -INFINITY, -INFINITY, -INFINITY};
    float l[4] = {};

    for (int k0 = 0; k0 < Nn; k0 += 64) {
        __syncthreads();
        #pragma unroll
        for (int u = 0; u < 4; u++) {
            int idx = tid + 256 * u;
            int r = idx >> 4, c4 = (idx & 15) * 4;
            *(float4*)&smK[r * 68 + c4] = *(const float4*)&ktp [(size_t)r * Nn + k0 + c4];
            *(float4*)&smV[r * 68 + c4] = *(const float4*)&vptr[(size_t)(k0 + r) * HDIM + c4];
        }
        if (tid < 64) {
            int i = b * Nn + k0 + tid;
            bool masked = (mask_w == 1) ? (mask[i] != 0)
                                        : (((const unsigned int*)mask)[i] != 0u);
            smMsk[tid] = masked ? -INFINITY : 0.f;
        }
        __syncthreads();

        float s[4][4] = {};
        #pragma unroll 8
        for (int d0 = 0; d0 < 64; d0 += 4) {
            float4 k0v = *(const float4*)&smK[(d0+0) * 68 + tx4];
            float4 k1v = *(const float4*)&smK[(d0+1) * 68 + tx4];
            float4 k2v = *(const float4*)&smK[(d0+2) * 68 + tx4];
            float4 k3v = *(const float4*)&smK[(d0+3) * 68 + tx4];
            #pragma unroll
            for (int i = 0; i < 4; i++) {
                float4 qq = *(const float4*)&smQ[(ty4 + i) * 68 + d0];
                s[i][0] += qq.x*k0v.x + qq.y*k1v.x + qq.z*k2v.x + qq.w*k3v.x;
                s[i][1] += qq.x*k0v.y + qq.y*k1v.y + qq.z*k2v.y + qq.w*k3v.y;
                s[i][2] += qq.x*k0v.z + qq.y*k1v.z + qq.z*k2v.z + qq.w*k3v.z;
                s[i][3] += qq.x*k0v.w + qq.y*k1v.w + qq.z*k2v.w + qq.w*k3v.w;
            }
        }
        #pragma unroll
        for (int i = 0; i < 4; i++) {
            const int* dp = dist + ((size_t)(b * Nn + q0 + ty4 + i)) * Nn + k0 + tx4;
            int4 dv = *(const int4*)dp;
            int d0 = min(max(dv.x, 0), 31), d1 = min(max(dv.y, 0), 31);
            int d2 = min(max(dv.z, 0), 31), d3 = min(max(dv.w, 0), 31);
            s[i][0] = s[i][0] * SCALE + smBT[d0] + smMsk[tx4 + 0];
            s[i][1] = s[i][1] * SCALE + smBT[d1] + smMsk[tx4 + 1];
            s[i][2] = s[i][2] * SCALE + smBT[d2] + smMsk[tx4 + 2];
            s[i][3] = s[i][3] * SCALE + smBT[d3] + smMsk[tx4 + 3];
        }
        #pragma unroll
        for (int i = 0; i < 4; i++) {
            float tm = fmaxf(fmaxf(s[i][0], s[i][1]), fmaxf(s[i][2], s[i][3]));
            #pragma unroll
            for (int off = 8; off; off >>= 1)
                tm = fmaxf(tm, __shfl_xor_sync(0xffffffffu, tm, off));
            float mo = m[i];
            float mn = fmaxf(mo, tm);
            float al   = (mn == -INFINITY) ? 0.f : __expf(mo - mn);
            float mred = (mn == -INFINITY) ? 0.f : mn;
            float sum = 0.f;
            int row = ty4 + i;
            #pragma unroll
            for (int j = 0; j < 4; j++) {
                float p = __expf(s[i][j] - mred);
                smS[row * 68 + tx4 + j] = p;
                sum += p;
                o[i][j] *= al;
            }
            #pragma unroll
            for (int off = 8; off; off >>= 1)
                sum += __shfl_xor_sync(0xffffffffu, sum, off);
            l[i] = l[i] * al + sum;
            m[i] = mn;
        }
        __syncthreads();

        #pragma unroll 8
        for (int j0 = 0; j0 < 64; j0 += 4) {
            float4 v0 = *(const float4*)&smV[(j0+0) * 68 + tx4];
            float4 v1 = *(const float4*)&smV[(j0+1) * 68 + tx4];
            float4 v2 = *(const float4*)&smV[(j0+2) * 68 + tx4];
            float4 v3 = *(const float4*)&smV[(j0+3) * 68 + tx4];
            #pragma unroll
            for (int i = 0; i < 4; i++) {
                float4 pp = *(const float4*)&smS[(ty4 + i) * 68 + j0];
                o[i][0] += pp.x*v0.x + pp.y*v1.x + pp.z*v2.x + pp.w*v3.x;
                o[i][1] += pp.x*v0.y + pp.y*v1.y + pp.z*v2.y + pp.w*v3.y;
                o[i][2] += pp.x*v0.z + pp.y*v1.z + pp.z*v2.z + pp.w*v3.z;
                o[i][3] += pp.x*v0.w + pp.y*v1.w + pp.z*v2.w + pp.w*v3.w;
            }
        }
    }
    #pragma unroll
    for (int i = 0; i < 4; i++) {
        int row = ty4 + i;
        float inv = (l[i] > 0.f) ? 1.f / l[i] : 0.f;
        float4 r4 = make_float4(o[i][0] * inv, o[i][1] * inv,
                                o[i][2] * inv, o[i][3] * inv);
        *(float4*)&g_o[((size_t)(b * Nn + q0 + row)) * Dd + h * HDIM + tx4] = r4;
    }
}

// ---------------------------------------------------------------------------
extern "C" void kernel_launch(void* const* d_in, const int* in_sizes, int n_in,
                              void* d_out, int out_size)
{
    const float*         x          = (const float*)d_in[0];
    const int*           dist       = (const int*)d_in[1];
    const unsigned char* mask       = (const unsigned char*)d_in[2];
    const float*         qkv_w      = (const float*)d_in[3];
    const float*         qkv_b      = (const float*)d_in[4];
    const float*         out_w      = (const float*)d_in[5];
    const float*         out_b      = (const float*)d_in[6];
    const float*         bias_table = (const float*)d_in[7];
    float*               out        = (float*)d_out;

    cudaFuncSetAttribute(attn_kernel,
                         cudaFuncAttributeMaxDynamicSharedMemorySize, ATTN_SMEM_BYTES);
    cudaFuncSetAttribute(hmma_proj_kernel<0>,
                         cudaFuncAttributeMaxDynamicSharedMemorySize, HMMA_SMEM_BYTES);
    cudaFuncSetAttribute(hmma_proj_kernel<1>,
                         cudaFuncAttributeMaxDynamicSharedMemorySize, HMMA_SMEM_BYTES);

    detect_mask_kernel<<<1, 256>>>(mask);

    __nv_bfloat16 *xhi, *xlo, *ohi, *olo, *wqh, *wql, *woh, *wol;
    cudaGetSymbolAddress((void**)&xhi, g_xhi);  cudaGetSymbolAddress((void**)&xlo, g_xlo);
    cudaGetSymbolAddress((void**)&ohi, g_ohi);  cudaGetSymbolAddress((void**)&olo, g_olo);
    cudaGetSymbolAddress((void**)&wqh, g_wqT_hi); cudaGetSymbolAddress((void**)&wql, g_wqT_lo);
    cudaGetSymbolAddress((void**)&woh, g_woT_hi); cudaGetSymbolAddress((void**)&wol, g_woT_lo);
    float* o32; cudaGetSymbolAddress((void**)&o32, g_o);

    const int nx = Bc * Nn * Dd;   // 3,145,728
    split_fp32_kernel<<<(nx + 255) / 256, 256>>>(x, xhi, xlo, nx);
    tsplit_kernel<<<dim3(3 * Dd / 32, Dd / 32), 256>>>(qkv_w, wqh, wql, Dd, 3 * Dd);
    tsplit_kernel<<<dim3(Dd / 32, Dd / 32), 256>>>(out_w, woh, wol, Dd, Dd);

    hmma_proj_kernel<0><<<dim3(3 * Dd / 128, Bc * Nn / 128), 256, HMMA_SMEM_BYTES>>>(
        xhi, xlo, wqh, wql, qkv_b, nullptr);

    attn_kernel<<<dim3(Nn / 64, Bc * Hh), 256, ATTN_SMEM_BYTES>>>(dist, mask, bias_table);

    split_fp32_kernel<<<(nx + 255) / 256, 256>>>(o32, ohi, olo, nx);
    hmma_proj_kernel<1><<<dim3(Dd / 128, Bc * Nn / 128), 256, HMMA_SMEM_BYTES>>>(
        ohi, olo, woh, wol, out_b, out);
}